// round 5
// baseline (speedup 1.0000x reference)
#include <cuda_runtime.h>
#include <cstdint>

// GRU: B=64, T=2048, I=256, H=256
// out = concat( out[B,T,H], hN[B,H] ) fp32
//
// Design: 16 clusters x 8 CTAs (128 SMs). Cluster c owns batches [4c,4c+4).
// CTA rank r owns j in [32r,32r+32) and gate rows {j, 256+j, 512+j} of the
// fused weight [W_hh | W_ih] (96 rows x 512 cols fp32 = 192KB in SMEM).
// Per step: GEMM gh/gi slices -> local GRU elementwise for its j-slice ->
// broadcast new h (32 floats/batch) to all 8 CTAs' A-panels via DSMEM ->
// cluster.sync. x_{t+1} prefetched with cp.async into the A-panel x-half.

static constexpr int B_  = 64;
static constexpr int T_  = 2048;
static constexpr int I_  = 256;
static constexpr int H_  = 256;

static constexpr int CL      = 8;    // cluster size
static constexpr int NB      = 4;    // batches per cluster
static constexpr int NCL     = 16;   // clusters
static constexpr int THREADS = 192;
static constexpr int APS     = 520;  // A-panel row stride in floats (pad for banks)
static constexpr int RPC     = 96;   // weight rows per CTA
static constexpr int NK4     = 128;  // float4 chunks along K=512

// SMEM layout (floats)
static constexpr int OFF_W    = 0;                       // 96*512 = 49152
static constexpr int OFF_AP   = 49152;                   // 2*4*520 = 4160
static constexpr int OFF_ACCH = OFF_AP + 2 * NB * APS;   // 384
static constexpr int OFF_ACCI = OFF_ACCH + RPC * NB;     // 384
static constexpr int OFF_BH   = OFF_ACCI + RPC * NB;     // 96
static constexpr int OFF_BI   = OFF_BH + RPC;            // 96
static constexpr int SMEM_FLOATS = OFF_BI + RPC;         // 54272
static constexpr int SMEM_BYTES  = SMEM_FLOATS * 4;      // 217088

typedef unsigned long long u64;

__device__ __forceinline__ void fma2(u64 &acc, u64 a, u64 b) {
    asm("fma.rn.f32x2 %0, %1, %2, %0;" : "+l"(acc) : "l"(a), "l"(b));
}
__device__ __forceinline__ float sum2(u64 v) {
    float lo, hi;
    asm("mov.b64 {%0,%1}, %2;" : "=f"(lo), "=f"(hi) : "l"(v));
    return lo + hi;
}
__device__ __forceinline__ uint32_t smem_u32(const void* p) {
    return (uint32_t)__cvta_generic_to_shared(p);
}
__device__ __forceinline__ void st_remote_f32(uint32_t laddr, int rank, float v) {
    uint32_t raddr;
    asm("mapa.shared::cluster.u32 %0, %1, %2;" : "=r"(raddr) : "r"(laddr), "r"(rank));
    asm volatile("st.shared::cluster.f32 [%0], %1;" :: "r"(raddr), "f"(v));
}
__device__ __forceinline__ void cluster_sync_() {
    asm volatile("barrier.cluster.arrive.aligned;" ::: "memory");
    asm volatile("barrier.cluster.wait.aligned;" ::: "memory");
}
__device__ __forceinline__ uint32_t ctarank_() {
    uint32_t r;
    asm("mov.u32 %0, %%cluster_ctarank;" : "=r"(r));
    return r;
}
__device__ __forceinline__ float sigmoidf_(float x) {
    return 1.0f / (1.0f + __expf(-x));
}

__global__ void __launch_bounds__(THREADS, 1) __cluster_dims__(CL, 1, 1)
gru_persistent_kernel(const float* __restrict__ x,
                      const float* __restrict__ h0,
                      const float* __restrict__ Wih,
                      const float* __restrict__ bih,
                      const float* __restrict__ Whh,
                      const float* __restrict__ bhh,
                      float* __restrict__ out,
                      int out_size)
{
    extern __shared__ float smem[];
    float* Ws   = smem + OFF_W;     // [k4][96 rows][4 floats]
    float* Ap   = smem + OFF_AP;    // [2 parity][NB][APS]; [0:256)=h, [256:512)=x
    float* accH = smem + OFF_ACCH;  // [96][4]
    float* accI = smem + OFF_ACCI;  // [96][4]
    float* bHs  = smem + OFF_BH;    // [96]
    float* bIs  = smem + OFF_BI;    // [96]

    const int tid  = threadIdx.x;
    const int rank = (int)ctarank_();
    const int b0   = (blockIdx.x >> 3) * NB;   // first global batch of this cluster

    const uint32_t ap_u32 = smem_u32(Ap);

    // ---- init: load weight slice [96 rows x 512] into SMEM, layout Ws[k4][lr][4]
    // row lr: gate = lr>>5, jj = lr&31, global row g = gate*256 + rank*32 + jj
    for (int idx = tid; idx < RPC * NK4; idx += THREADS) {
        int lr = idx >> 7;          // 0..95
        int k4 = idx & 127;         // 0..127
        int g  = ((lr >> 5) << 8) + (rank << 5) + (lr & 31);
        int k0 = k4 << 2;
        float4 v;
        if (k0 < 256) v = *(const float4*)(Whh + (size_t)g * H_ + k0);
        else          v = *(const float4*)(Wih + (size_t)g * I_ + (k0 - 256));
        *(float4*)(Ws + ((k4 * RPC + lr) << 2)) = v;
    }
    for (int lr = tid; lr < RPC; lr += THREADS) {
        int g = ((lr >> 5) << 8) + (rank << 5) + (lr & 31);
        bHs[lr] = bhh[g];
        bIs[lr] = bih[g];
    }
    // h0 (full 256 per batch) and x_0 into parity-0 A-panel
    for (int i4 = tid; i4 < NB * 64; i4 += THREADS) {
        int b = i4 >> 6, kk = i4 & 63;
        *(float4*)(Ap + b * APS + (kk << 2)) =
            *(const float4*)(h0 + (size_t)(b0 + b) * H_ + (kk << 2));
    }
    for (int i4 = tid; i4 < NB * 64; i4 += THREADS) {
        int b = i4 >> 6, kk = i4 & 63;
        *(float4*)(Ap + b * APS + 256 + (kk << 2)) =
            *(const float4*)(x + ((size_t)(b0 + b) * T_ + 0) * I_ + (kk << 2));
    }
    cluster_sync_();

    // GEMM thread mapping: b = tid&3, rh = tid>>2 in [0,48); rows {rh, rh+48}
    const int gb  = tid & 3;
    const int rh  = tid >> 2;
    const int lr0 = rh;
    const int lr1 = rh + 48;

    const size_t BTH = (size_t)B_ * T_ * H_;

    for (int t = 0; t < T_; ++t) {
        const int p  = t & 1;
        const int pn = p ^ 1;

        // -- prefetch x_{t+1} into Ap[pn] x-half (overlaps with GEMM)
        if (t + 1 < T_) {
            for (int i4 = tid; i4 < NB * 64; i4 += THREADS) {
                int b = i4 >> 6, kk = i4 & 63;
                const float* g = x + ((size_t)(b0 + b) * T_ + (t + 1)) * I_ + (kk << 2);
                uint32_t s = ap_u32 + (uint32_t)((pn * (NB * APS) + b * APS + 256 + (kk << 2)) * 4);
                asm volatile("cp.async.ca.shared.global [%0], [%1], 16;" :: "r"(s), "l"(g));
            }
        }
        asm volatile("cp.async.commit_group;");

        // -- GEMM: acc_h over k<256 (h part), acc_i over k>=256 (x part)
        const ulonglong2* A2 = (const ulonglong2*)(Ap + p * (NB * APS) + gb * APS);
        const ulonglong2* W2 = (const ulonglong2*)Ws;

        u64 h0a = 0, h0b = 0, h1a = 0, h1b = 0;
        u64 i0a = 0, i0b = 0, i1a = 0, i1b = 0;

        #pragma unroll 8
        for (int k4 = 0; k4 < 64; ++k4) {
            ulonglong2 a  = A2[k4];
            ulonglong2 w0 = W2[k4 * RPC + lr0];
            ulonglong2 w1 = W2[k4 * RPC + lr1];
            fma2(h0a, a.x, w0.x); fma2(h0b, a.y, w0.y);
            fma2(h1a, a.x, w1.x); fma2(h1b, a.y, w1.y);
        }
        #pragma unroll 8
        for (int k4 = 64; k4 < 128; ++k4) {
            ulonglong2 a  = A2[k4];
            ulonglong2 w0 = W2[k4 * RPC + lr0];
            ulonglong2 w1 = W2[k4 * RPC + lr1];
            fma2(i0a, a.x, w0.x); fma2(i0b, a.y, w0.y);
            fma2(i1a, a.x, w1.x); fma2(i1b, a.y, w1.y);
        }

        accH[(lr0 << 2) + gb] = sum2(h0a) + sum2(h0b);
        accH[(lr1 << 2) + gb] = sum2(h1a) + sum2(h1b);
        accI[(lr0 << 2) + gb] = sum2(i0a) + sum2(i0b);
        accI[(lr1 << 2) + gb] = sum2(i1a) + sum2(i1b);

        __syncthreads();

        // -- GRU elementwise for this CTA's 4 batches x 32 j  (tid < 128)
        if (tid < 128) {
            const int b  = tid & 3;
            const int jj = tid >> 2;           // 0..31
            const int jg = (rank << 5) + jj;   // global j

            float gr = accH[(jj << 2) + b]        + bHs[jj];
            float ir = accI[(jj << 2) + b]        + bIs[jj];
            float gc = accH[((32 + jj) << 2) + b] + bHs[32 + jj];
            float ic = accI[((32 + jj) << 2) + b] + bIs[32 + jj];
            float gu = accH[((64 + jj) << 2) + b] + bHs[64 + jj];
            float iu = accI[((64 + jj) << 2) + b] + bIs[64 + jj];

            float r = sigmoidf_(ir + gr);
            float u = sigmoidf_(iu + gu);
            float n = tanhf(ic + r * gc);

            float hold = Ap[p * (NB * APS) + b * APS + jg];
            float hy   = hold + u * (n - hold);

            out[((size_t)(b0 + b) * T_ + t) * H_ + jg] = hy;

            // broadcast new h to all 8 CTAs' next-parity A-panels (incl. self)
            uint32_t laddr = ap_u32 + (uint32_t)((pn * (NB * APS) + b * APS + jg) * 4);
            #pragma unroll
            for (int pr = 0; pr < CL; ++pr) {
                st_remote_f32(laddr, pr, hy);
            }
        }

        asm volatile("cp.async.wait_group 0;" ::: "memory");
        cluster_sync_();   // release: DSMEM h-broadcast visible to peers
    }

    // -- final hidden state hN = h after step T-1, lives in parity 0 (T even)
    if (out_size >= (int)(BTH + (size_t)B_ * H_)) {
        for (int i = tid; i < NB * H_; i += THREADS) {
            int b = i >> 8, j = i & 255;
            out[BTH + (size_t)(b0 + b) * H_ + j] = Ap[b * APS + j];
        }
    }
}

extern "C" void kernel_launch(void* const* d_in, const int* in_sizes, int n_in,
                              void* d_out, int out_size) {
    const float* x    = (const float*)d_in[0];
    const float* h0   = (const float*)d_in[1];
    const float* Wih  = (const float*)d_in[2];
    const float* bih  = (const float*)d_in[3];
    const float* Whh  = (const float*)d_in[4];
    const float* bhh  = (const float*)d_in[5];
    float* out = (float*)d_out;

    cudaFuncSetAttribute(gru_persistent_kernel,
                         cudaFuncAttributeMaxDynamicSharedMemorySize, SMEM_BYTES);

    gru_persistent_kernel<<<NCL * CL, THREADS, SMEM_BYTES>>>(
        x, h0, Wih, bih, Whh, bhh, out, out_size);
}